// round 7
// baseline (speedup 1.0000x reference)
#include <cuda_runtime.h>
#include <cstdint>
#include <math.h>

#define DEG 3
#define NM 32          // MU_MAX = MV_MAX
#define NU 64          // OUT_U = OUT_V
#define BATCH 1024
#define GRID 512       // persistent: each block handles 2 samples, single wave
#define EPSI 1e-5f

// per-block partials: x = surf-sq-err sum, y = ctrl-sq-err sum, z = mask sum
__device__ float4 g_part[GRID];
__device__ unsigned g_count = 0;   // last-block counter; reset each launch

// clamped open-uniform knot, n_valid = m ctrl pts (matches reference padding)
__device__ __forceinline__ float kvf(int k, int m) {
    if (k <= DEG) return 0.0f;
    if (k >= m)   return 1.0f;
    return (float)k / (float)(m + DEG);
}

// ---------------- smem layout (floats) ----------------
//  sCf   float[3072]    : 0       ctrl_pred packed xyz (12 KB)
//  sTx   float[64*32]   : 3072
//  sTy   float[64*32]   : 5120
//  sTz   float[64*32]   : 7168
//  wU4   float4[64]     : 9216    (denominator-folded weights)
//  wV4   float4[64]     : 9472
//  baseU int[64]        : 9728
//  baseV int[64]        : 9792
//  total 9856 floats = 39424 B
#define SMEM_FLOATS 9856

__global__ __launch_bounds__(256, 4)
void surf_loss_kernel(const float* __restrict__ ctrl_pred,
                      const float* __restrict__ ctrl_gt,
                      const float* __restrict__ mask,
                      const float* __restrict__ xyz,
                      float* __restrict__ out) {
    extern __shared__ float sm[];
    float*  sCf   = sm;
    float*  sTx   = sm + 3072;
    float*  sTy   = sm + 5120;
    float*  sTz   = sm + 7168;
    float4* wU4   = (float4*)(sm + 9216);
    float4* wV4   = (float4*)(sm + 9472);
    int*    baseU = (int*)(sm + 9728);
    int*    baseV = (int*)(sm + 9792);

    __shared__ float rS[8], rC[8], rM[8];
    __shared__ int s_last;

    const int tid  = threadIdx.x;
    const int lane = tid & 31;
    const int warp = tid >> 5;

    float lsTot = 0.0f, lcTot = 0.0f, lmTot = 0.0f;

    for (int b = blockIdx.x; b < BATCH; b += GRID) {

        // ---- ragged sizes: every warp computes them (warp-local, no barrier) ----
        const float* mk = mask + (size_t)b * (NM * NM);
        unsigned bmv = __ballot_sync(0xffffffffu, mk[lane] > 0.0f);        // row 0 -> mv
        unsigned bmu = __ballot_sync(0xffffffffu, mk[lane * NM] > 0.0f);   // col 0 -> mu
        const int mu = max(__popc(bmu), DEG + 1);
        const int mv = max(__popc(bmv), DEG + 1);
        if (tid == 0) lmTot += (float)(mu * mv);   // ONCE per block (R6 bug: was all threads)

        // ---- ctrl MSE: 4 consecutive points / thread, 3 float4 loads each ----
        {
            const float4* cp4 = (const float4*)(ctrl_pred + (size_t)b * (NM * NM * 3));
            const float4* cg4 = (const float4*)(ctrl_gt   + (size_t)b * (NM * NM * 3));
            float4* sC4w = (float4*)sCf;
            int k = 3 * tid;
            float4 p0 = cp4[k], p1 = cp4[k + 1], p2 = cp4[k + 2];
            float4 g0 = cg4[k], g1 = cg4[k + 1], g2 = cg4[k + 2];
            sC4w[k] = p0; sC4w[k + 1] = p1; sC4w[k + 2] = p2;
            int c0 = 4 * tid;                  // first of 4 points
            float d;
            float ss0, ss1, ss2, ss3;
            d = p0.x - g0.x; ss0  = d * d;
            d = p0.y - g0.y; ss0 += d * d;
            d = p0.z - g0.z; ss0 += d * d;
            d = p0.w - g0.w; ss1  = d * d;
            d = p1.x - g1.x; ss1 += d * d;
            d = p1.y - g1.y; ss1 += d * d;
            d = p1.z - g1.z; ss2  = d * d;
            d = p1.w - g1.w; ss2 += d * d;
            d = p2.x - g2.x; ss2 += d * d;
            d = p2.y - g2.y; ss3  = d * d;
            d = p2.z - g2.z; ss3 += d * d;
            d = p2.w - g2.w; ss3 += d * d;
            int i0 = (c0    ) >> 5, j0 = (c0    ) & 31;
            int i1 = (c0 + 1) >> 5, j1 = (c0 + 1) & 31;
            int i2 = (c0 + 2) >> 5, j2 = (c0 + 2) & 31;
            int i3 = (c0 + 3) >> 5, j3 = (c0 + 3) & 31;
            if (i0 < mu && j0 < mv) lcTot += ss0;
            if (i1 < mu && j1 < mv) lcTot += ss1;
            if (i2 < mu && j2 < mv) lcTot += ss2;
            if (i3 < mu && j3 < mv) lcTot += ss3;
        }

        // ---- local de Boor: 4 nonzero weights, denominator folded in ----
        if (tid < 128) {
            int dim = tid >> 6, g = tid & 63;
            int m = dim ? mv : mu;
            float x = EPSI + ((1.0f - 2.0f * EPSI) / 63.0f) * (float)g;
            int s = (int)(x * (float)(m + DEG));
            s = max(s, DEG); s = min(s, m - 1);
            while (s < m - 1 && x >= kvf(s + 1, m)) s++;
            while (s > DEG && x < kvf(s, m)) s--;
            float N[4]; N[0] = 1.0f; N[1] = N[2] = N[3] = 0.0f;
            float left[4], right[4];
#pragma unroll
            for (int d = 1; d <= DEG; d++) {
                left[d]  = x - kvf(s + 1 - d, m);
                right[d] = kvf(s + d, m) - x;
                float saved = 0.0f;
#pragma unroll
                for (int r = 0; r < d; r++) {
                    float tmp = N[r] / (right[r + 1] + left[d - r]);
                    N[r] = saved + right[r + 1] * tmp;
                    saved = left[d - r] * tmp;
                }
                N[d] = saved;
            }
            float inv = 1.0f / (N[0] + N[1] + N[2] + N[3]);  // partition denom
            float4 w = make_float4(N[0] * inv, N[1] * inv, N[2] * inv, N[3] * inv);
            if (dim == 0) { wU4[g] = w; baseU[g] = s - DEG; }
            else          { wV4[g] = w; baseV[g] = s - DEG; }
        }
        __syncthreads();

        // ---- stage 1: T[u][j] = 4 weighted ctrl rows. warp=u-group, lane=j ----
        if (lane < mv) {
#pragma unroll
            for (int u = warp; u < NU; u += 8) {
                float4 w = wU4[u];
                const float* cc = &sCf[(baseU[u] * NM + lane) * 3];
                // bank = (3*lane + d) mod 32, gcd(3,32)=1 -> conflict-free
                float ax = w.x * cc[0] + w.y * cc[96] + w.z * cc[192] + w.w * cc[288];
                float ay = w.x * cc[1] + w.y * cc[97] + w.z * cc[193] + w.w * cc[289];
                float az = w.x * cc[2] + w.y * cc[98] + w.z * cc[194] + w.w * cc[290];
                sTx[u * NM + lane] = ax;
                sTy[u * NM + lane] = ay;
                sTz[u * NM + lane] = az;
            }
        }
        __syncthreads();

        // ---- stage 2: surface eval (weights pre-normalized) + MSE ----
        {
            float4 w0 = wV4[lane], w1 = wV4[lane + 32];
            int    j0 = baseV[lane], j1 = baseV[lane + 32];
            const float* xb = xyz + (size_t)b * (NU * NU * 3);
#pragma unroll 2
            for (int u = warp; u < NU; u += 8) {
                // hoist gmem loads to iteration top for MLP
                const float* x0 = xb + (size_t)(u * NU + lane) * 3;
                float X0 = x0[0], X1 = x0[1], X2 = x0[2];
                float X3 = x0[96], X4 = x0[97], X5 = x0[98];
                const float* tx = &sTx[u * NM];
                const float* ty = &sTy[u * NM];
                const float* tz = &sTz[u * NM];
                float n00 = w0.x * tx[j0] + w0.y * tx[j0 + 1] + w0.z * tx[j0 + 2] + w0.w * tx[j0 + 3];
                float n01 = w0.x * ty[j0] + w0.y * ty[j0 + 1] + w0.z * ty[j0 + 2] + w0.w * ty[j0 + 3];
                float n02 = w0.x * tz[j0] + w0.y * tz[j0 + 1] + w0.z * tz[j0 + 2] + w0.w * tz[j0 + 3];
                float n10 = w1.x * tx[j1] + w1.y * tx[j1 + 1] + w1.z * tx[j1 + 2] + w1.w * tx[j1 + 3];
                float n11 = w1.x * ty[j1] + w1.y * ty[j1 + 1] + w1.z * ty[j1 + 2] + w1.w * ty[j1 + 3];
                float n12 = w1.x * tz[j1] + w1.y * tz[j1 + 1] + w1.z * tz[j1 + 2] + w1.w * tz[j1 + 3];
                float e;
                e = n00 - X0; lsTot += e * e;
                e = n01 - X1; lsTot += e * e;
                e = n02 - X2; lsTot += e * e;
                e = n10 - X3; lsTot += e * e;
                e = n11 - X4; lsTot += e * e;
                e = n12 - X5; lsTot += e * e;
                // NaN/Inf in surf propagates into lsTot; guard evaluated at end
            }
        }
        __syncthreads();   // protect smem (wU/wV/base/sT) before next sample
    }

    // ---- block reduction -> per-block partial ----
#pragma unroll
    for (int o = 16; o > 0; o >>= 1) {
        lsTot += __shfl_down_sync(0xffffffffu, lsTot, o);
        lcTot += __shfl_down_sync(0xffffffffu, lcTot, o);
    }
    if (lane == 0) { rS[warp] = lsTot; rC[warp] = lcTot; rM[warp] = (warp == 0) ? lmTot : 0.0f; }
    __syncthreads();
    if (tid == 0) {
        float S = 0.0f, C = 0.0f;
#pragma unroll
        for (int i = 0; i < 8; i++) { S += rS[i]; C += rC[i]; }
        g_part[blockIdx.x] = make_float4(S, C, rM[0], 0.0f);
        __threadfence();
        unsigned t = atomicAdd(&g_count, 1u);
        s_last = (t == GRID - 1) ? 1 : 0;
    }
    __syncthreads();

    // ---- last block: global reduction + output (fused finalize) ----
    if (s_last) {
        __threadfence();   // ensure visibility of all g_part writes
        double s = 0.0, c = 0.0, m = 0.0;
#pragma unroll
        for (int i = tid; i < GRID; i += 256) {
            float4 p = g_part[i];
            s += (double)p.x; c += (double)p.y; m += (double)p.z;
        }
#pragma unroll
        for (int o = 16; o > 0; o >>= 1) {
            s += __shfl_down_sync(0xffffffffu, s, o);
            c += __shfl_down_sync(0xffffffffu, c, o);
            m += __shfl_down_sync(0xffffffffu, m, o);
        }
        __shared__ double dS[8], dC[8], dM[8];
        if (lane == 0) { dS[warp] = s; dC[warp] = c; dM[warp] = m; }
        __syncthreads();
        if (tid == 0) {
            double S = 0.0, C = 0.0, M = 0.0;
#pragma unroll
            for (int i = 0; i < 8; i++) { S += dS[i]; C += dC[i]; M += dM[i]; }
            double denom = M * 3.0; if (denom < 1.0) denom = 1.0;
            double loss_ctrl = C / denom;
            double loss_surf = S / (double)((long long)BATCH * NU * NU * 3);
            float lcf = (float)loss_ctrl;
            float lsf = (float)loss_surf;
            out[0] = lcf + lsf;                 // total (pre nan-guard, W=1)
            out[1] = lcf;                       // loss_ctrl
            unsigned ub = __float_as_uint(lsf);
            bool bad = ((ub & 0x7f800000u) == 0x7f800000u);
            out[2] = bad ? 1e6f : lsf;          // surf_mse (guarded)
            g_count = 0;                        // reset for next graph replay
        }
    }
}

extern "C" void kernel_launch(void* const* d_in, const int* in_sizes, int n_in,
                              void* d_out, int out_size) {
    const float* ctrl_pred = (const float*)d_in[0];   // (B,32,32,3)
    const float* ctrl_gt   = (const float*)d_in[1];   // (B,32,32,3)
    const float* mask      = (const float*)d_in[2];   // (B,32,32)
    const float* xyz       = (const float*)d_in[3];   // (B,64,64,3)
    float* out = (float*)d_out;

    size_t smem_bytes = SMEM_FLOATS * sizeof(float);  // 39424 B
    cudaFuncSetAttribute(surf_loss_kernel,
                         cudaFuncAttributeMaxDynamicSharedMemorySize,
                         (int)smem_bytes);

    surf_loss_kernel<<<GRID, 256, smem_bytes>>>(ctrl_pred, ctrl_gt, mask, xyz, out);
}

// round 10
// speedup vs baseline: 1.1445x; 1.1445x over previous
#include <cuda_runtime.h>
#include <cstdint>
#include <math.h>

#define DEG 3
#define NM 32          // MU_MAX = MV_MAX
#define NU 64          // OUT_U = OUT_V
#define BATCH 1024
#define EPSI 1e-5f

// per-block partials: x = surf-sq-err sum, y = ctrl-sq-err sum, z = mask sum
__device__ float4 g_part[BATCH];
__device__ unsigned g_count = 0;   // last-block counter; reset each launch

// clamped open-uniform knot, n_valid = m ctrl pts (matches reference padding)
__device__ __forceinline__ float kvf(int k, int m) {
    if (k <= DEG) return 0.0f;
    if (k >= m)   return 1.0f;
    return (float)k / (float)(m + DEG);
}

// ---------------- smem layout (floats) ----------------
//  sCf   float[3072]    : 0       ctrl_pred packed xyz (12 KB)
//  sTx   float[64*32]   : 3072
//  sTy   float[64*32]   : 5120
//  sTz   float[64*32]   : 7168
//  wU4   float4[64]     : 9216    (denominator-folded weights)
//  wV4   float4[64]     : 9472
//  baseU int[64]        : 9728
//  baseV int[64]        : 9792
//  total 9856 floats = 39424 B
#define SMEM_FLOATS 9856

__global__ __launch_bounds__(256, 4)
void surf_loss_kernel(const float* __restrict__ ctrl_pred,
                      const float* __restrict__ ctrl_gt,
                      const float* __restrict__ mask,
                      const float* __restrict__ xyz,
                      float* __restrict__ out) {
    extern __shared__ float sm[];
    float*  sCf   = sm;
    float*  sTx   = sm + 3072;
    float*  sTy   = sm + 5120;
    float*  sTz   = sm + 7168;
    float4* wU4   = (float4*)(sm + 9216);
    float4* wV4   = (float4*)(sm + 9472);
    int*    baseU = (int*)(sm + 9728);
    int*    baseV = (int*)(sm + 9792);

    __shared__ float rS[8], rC[8];
    __shared__ int s_last;

    const int b    = blockIdx.x;
    const int tid  = threadIdx.x;
    const int lane = tid & 31;
    const int warp = tid >> 5;

    // ---- ragged sizes: every warp computes them (warp-local, no barrier) ----
    const float* mk = mask + (size_t)b * (NM * NM);
    unsigned bmv = __ballot_sync(0xffffffffu, mk[lane] > 0.0f);        // row 0 -> mv
    unsigned bmu = __ballot_sync(0xffffffffu, mk[lane * NM] > 0.0f);   // col 0 -> mu
    const int mu = max(__popc(bmu), DEG + 1);
    const int mv = max(__popc(bmv), DEG + 1);

    // ---- ctrl MSE: 4 consecutive points / thread, 3 float4 loads each ----
    float lc = 0.0f;
    {
        const float4* cp4 = (const float4*)(ctrl_pred + (size_t)b * (NM * NM * 3));
        const float4* cg4 = (const float4*)(ctrl_gt   + (size_t)b * (NM * NM * 3));
        float4* sC4w = (float4*)sCf;
        int k = 3 * tid;
        float4 p0 = __ldcs(&cp4[k]), p1 = __ldcs(&cp4[k + 1]), p2 = __ldcs(&cp4[k + 2]);
        float4 g0 = __ldcs(&cg4[k]), g1 = __ldcs(&cg4[k + 1]), g2 = __ldcs(&cg4[k + 2]);
        sC4w[k] = p0; sC4w[k + 1] = p1; sC4w[k + 2] = p2;
        int c0 = 4 * tid;                  // first of 4 points
        float d;
        float ss0, ss1, ss2, ss3;
        d = p0.x - g0.x; ss0  = d * d;
        d = p0.y - g0.y; ss0 += d * d;
        d = p0.z - g0.z; ss0 += d * d;
        d = p0.w - g0.w; ss1  = d * d;
        d = p1.x - g1.x; ss1 += d * d;
        d = p1.y - g1.y; ss1 += d * d;
        d = p1.z - g1.z; ss2  = d * d;
        d = p1.w - g1.w; ss2 += d * d;
        d = p2.x - g2.x; ss2 += d * d;
        d = p2.y - g2.y; ss3  = d * d;
        d = p2.z - g2.z; ss3 += d * d;
        d = p2.w - g2.w; ss3 += d * d;
        int i0 = (c0    ) >> 5, j0 = (c0    ) & 31;
        int i1 = (c0 + 1) >> 5, j1 = (c0 + 1) & 31;
        int i2 = (c0 + 2) >> 5, j2 = (c0 + 2) & 31;
        int i3 = (c0 + 3) >> 5, j3 = (c0 + 3) & 31;
        if (i0 < mu && j0 < mv) lc += ss0;
        if (i1 < mu && j1 < mv) lc += ss1;
        if (i2 < mu && j2 < mv) lc += ss2;
        if (i3 < mu && j3 < mv) lc += ss3;
    }

    // ---- local de Boor: 4 nonzero weights, denominator folded in ----
    if (tid < 128) {
        int dim = tid >> 6, g = tid & 63;
        int m = dim ? mv : mu;
        float x = EPSI + ((1.0f - 2.0f * EPSI) / 63.0f) * (float)g;
        int s = (int)(x * (float)(m + DEG));
        s = max(s, DEG); s = min(s, m - 1);
        while (s < m - 1 && x >= kvf(s + 1, m)) s++;
        while (s > DEG && x < kvf(s, m)) s--;
        float N[4]; N[0] = 1.0f; N[1] = N[2] = N[3] = 0.0f;
        float left[4], right[4];
#pragma unroll
        for (int d = 1; d <= DEG; d++) {
            left[d]  = x - kvf(s + 1 - d, m);
            right[d] = kvf(s + d, m) - x;
            float saved = 0.0f;
#pragma unroll
            for (int r = 0; r < d; r++) {
                float tmp = N[r] / (right[r + 1] + left[d - r]);
                N[r] = saved + right[r + 1] * tmp;
                saved = left[d - r] * tmp;
            }
            N[d] = saved;
        }
        float inv = 1.0f / (N[0] + N[1] + N[2] + N[3]);  // partition denom
        float4 w = make_float4(N[0] * inv, N[1] * inv, N[2] * inv, N[3] * inv);
        if (dim == 0) { wU4[g] = w; baseU[g] = s - DEG; }
        else          { wV4[g] = w; baseV[g] = s - DEG; }
    }
    __syncthreads();

    // ---- stage 1: T[u][j] = 4 weighted ctrl rows. warp=u-group, lane=j ----
    if (lane < mv) {
#pragma unroll
        for (int u = warp; u < NU; u += 8) {
            float4 w = wU4[u];
            const float* cc = &sCf[(baseU[u] * NM + lane) * 3];
            // bank = (3*lane + d) mod 32, gcd(3,32)=1 -> conflict-free
            float ax = w.x * cc[0] + w.y * cc[96] + w.z * cc[192] + w.w * cc[288];
            float ay = w.x * cc[1] + w.y * cc[97] + w.z * cc[193] + w.w * cc[289];
            float az = w.x * cc[2] + w.y * cc[98] + w.z * cc[194] + w.w * cc[290];
            sTx[u * NM + lane] = ax;
            sTy[u * NM + lane] = ay;
            sTz[u * NM + lane] = az;
        }
    }
    __syncthreads();

    // ---- stage 2: surface eval + MSE. lane handles v = 2*lane, 2*lane+1.
    //      xyz comes in as 3 contiguous aligned float2 per lane (LDG.64),
    //      software-pipelined with prefetch distance 1. ----
    float ls = 0.0f;
    {
        const int v0 = 2 * lane, v1 = v0 + 1;
        float4 w0 = wV4[v0],  w1 = wV4[v1];
        int    j0 = baseV[v0], j1 = baseV[v1];
        const float* xb = xyz + (size_t)b * (NU * NU * 3);

        // per-u base: xb + u*192 + 6*lane  (byte offset 768u + 24*lane, 8-aligned)
        const float2* p = (const float2*)(xb + warp * 192 + 6 * lane);
        float2 A0 = __ldcs(p), A1 = __ldcs(p + 1), A2 = __ldcs(p + 2);

#pragma unroll
        for (int k = 0; k < 8; k++) {
            int u = warp + 8 * k;
            float2 C0 = A0, C1 = A1, C2 = A2;
            if (k < 7) {
                const float2* pn = (const float2*)(xb + (u + 8) * 192 + 6 * lane);
                A0 = __ldcs(pn); A1 = __ldcs(pn + 1); A2 = __ldcs(pn + 2);
            }
            const float* tx = &sTx[u * NM];
            const float* ty = &sTy[u * NM];
            const float* tz = &sTz[u * NM];
            float n00 = w0.x * tx[j0] + w0.y * tx[j0 + 1] + w0.z * tx[j0 + 2] + w0.w * tx[j0 + 3];
            float n01 = w0.x * ty[j0] + w0.y * ty[j0 + 1] + w0.z * ty[j0 + 2] + w0.w * ty[j0 + 3];
            float n02 = w0.x * tz[j0] + w0.y * tz[j0 + 1] + w0.z * tz[j0 + 2] + w0.w * tz[j0 + 3];
            float n10 = w1.x * tx[j1] + w1.y * tx[j1 + 1] + w1.z * tx[j1 + 2] + w1.w * tx[j1 + 3];
            float n11 = w1.x * ty[j1] + w1.y * ty[j1 + 1] + w1.z * ty[j1 + 2] + w1.w * ty[j1 + 3];
            float n12 = w1.x * tz[j1] + w1.y * tz[j1 + 1] + w1.z * tz[j1 + 2] + w1.w * tz[j1 + 3];
            float e;
            e = n00 - C0.x; ls += e * e;   // point v0 = (C0.x, C0.y, C1.x)
            e = n01 - C0.y; ls += e * e;
            e = n02 - C1.x; ls += e * e;
            e = n10 - C1.y; ls += e * e;   // point v1 = (C1.y, C2.x, C2.y)
            e = n11 - C2.x; ls += e * e;
            e = n12 - C2.y; ls += e * e;
            // NaN/Inf in surf propagates into ls; guard evaluated at end
        }
    }

    // ---- block reduction -> per-block partial ----
#pragma unroll
    for (int o = 16; o > 0; o >>= 1) {
        ls += __shfl_down_sync(0xffffffffu, ls, o);
        lc += __shfl_down_sync(0xffffffffu, lc, o);
    }
    if (lane == 0) { rS[warp] = ls; rC[warp] = lc; }
    __syncthreads();
    if (tid == 0) {
        float S = 0.0f, C = 0.0f;
#pragma unroll
        for (int i = 0; i < 8; i++) { S += rS[i]; C += rC[i]; }
        g_part[b] = make_float4(S, C, (float)(mu * mv), 0.0f);
        __threadfence();
        unsigned t = atomicAdd(&g_count, 1u);
        s_last = (t == BATCH - 1) ? 1 : 0;
    }
    __syncthreads();

    // ---- last block: global reduction + output (fused finalize) ----
    if (s_last) {
        __threadfence();
        double s = 0.0, c = 0.0, m = 0.0;
#pragma unroll
        for (int i = tid; i < BATCH; i += 256) {
            float4 pt = g_part[i];
            s += (double)pt.x; c += (double)pt.y; m += (double)pt.z;
        }
#pragma unroll
        for (int o = 16; o > 0; o >>= 1) {
            s += __shfl_down_sync(0xffffffffu, s, o);
            c += __shfl_down_sync(0xffffffffu, c, o);
            m += __shfl_down_sync(0xffffffffu, m, o);
        }
        __shared__ double dS[8], dC[8], dM[8];
        if (lane == 0) { dS[warp] = s; dC[warp] = c; dM[warp] = m; }
        __syncthreads();
        if (tid == 0) {
            double S = 0.0, C = 0.0, M = 0.0;
#pragma unroll
            for (int i = 0; i < 8; i++) { S += dS[i]; C += dC[i]; M += dM[i]; }
            double denom = M * 3.0; if (denom < 1.0) denom = 1.0;
            double loss_ctrl = C / denom;
            double loss_surf = S / (double)((long long)BATCH * NU * NU * 3);
            float lcf = (float)loss_ctrl;
            float lsf = (float)loss_surf;
            out[0] = lcf + lsf;                 // total (pre nan-guard, W=1)
            out[1] = lcf;                       // loss_ctrl
            unsigned ub = __float_as_uint(lsf);
            bool bad = ((ub & 0x7f800000u) == 0x7f800000u);
            out[2] = bad ? 1e6f : lsf;          // surf_mse (guarded)
            g_count = 0;                        // reset for next graph replay
        }
    }
}

extern "C" void kernel_launch(void* const* d_in, const int* in_sizes, int n_in,
                              void* d_out, int out_size) {
    const float* ctrl_pred = (const float*)d_in[0];   // (B,32,32,3)
    const float* ctrl_gt   = (const float*)d_in[1];   // (B,32,32,3)
    const float* mask      = (const float*)d_in[2];   // (B,32,32)
    const float* xyz       = (const float*)d_in[3];   // (B,64,64,3)
    float* out = (float*)d_out;

    size_t smem_bytes = SMEM_FLOATS * sizeof(float);  // 39424 B
    cudaFuncSetAttribute(surf_loss_kernel,
                         cudaFuncAttributeMaxDynamicSharedMemorySize,
                         (int)smem_bytes);

    surf_loss_kernel<<<BATCH, 256, smem_bytes>>>(ctrl_pred, ctrl_gt, mask, xyz, out);
}

// round 11
// speedup vs baseline: 1.1580x; 1.0118x over previous
#include <cuda_runtime.h>
#include <cstdint>
#include <math.h>

#define DEG 3
#define NM 32          // MU_MAX = MV_MAX
#define NU 64          // OUT_U = OUT_V
#define BATCH 1024
#define EPSI 1e-5f

// per-block partials: x = surf-sq-err sum, y = ctrl-sq-err sum, z = mask sum
__device__ float4 g_part[BATCH];
__device__ unsigned g_count = 0;   // last-block counter; reset each launch

// clamped open-uniform knot, n_valid = m ctrl pts (matches reference padding)
__device__ __forceinline__ float kvf(int k, int m) {
    if (k <= DEG) return 0.0f;
    if (k >= m)   return 1.0f;
    return (float)k / (float)(m + DEG);
}

// ---------------- smem layout (floats) ----------------
//  sCf   float[3072]      : 0      ctrl_pred packed xyz (12 KB)
//  wU4   float4[64]       : 3072   (denominator-folded weights)
//  wV4   float4[64]       : 3328
//  baseU int[64]          : 3584
//  baseV int[64]          : 3648
//  sT    float[8][2][96]  : 3712   per-warp double-buffered T tile
//  total 5248 floats = 20992 B
#define SMEM_FLOATS 5248

__global__ __launch_bounds__(256, 5)
void surf_loss_kernel(const float* __restrict__ ctrl_pred,
                      const float* __restrict__ ctrl_gt,
                      const float* __restrict__ mask,
                      const float* __restrict__ xyz,
                      float* __restrict__ out) {
    extern __shared__ float sm[];
    float*  sCf   = sm;
    float4* wU4   = (float4*)(sm + 3072);
    float4* wV4   = (float4*)(sm + 3328);
    int*    baseU = (int*)(sm + 3584);
    int*    baseV = (int*)(sm + 3648);
    float*  sT    = sm + 3712;

    __shared__ float rS[8], rC[8];
    __shared__ int s_last;

    const int b    = blockIdx.x;
    const int tid  = threadIdx.x;
    const int lane = tid & 31;
    const int warp = tid >> 5;

    // ---- ragged sizes: every warp computes them (warp-local, no barrier) ----
    const float* mk = mask + (size_t)b * (NM * NM);
    unsigned bmv = __ballot_sync(0xffffffffu, mk[lane] > 0.0f);        // row 0 -> mv
    unsigned bmu = __ballot_sync(0xffffffffu, mk[lane * NM] > 0.0f);   // col 0 -> mu
    const int mu = max(__popc(bmu), DEG + 1);
    const int mv = max(__popc(bmv), DEG + 1);

    // ---- ctrl MSE: 4 consecutive points / thread, 3 float4 loads each ----
    float lc = 0.0f;
    {
        const float4* cp4 = (const float4*)(ctrl_pred + (size_t)b * (NM * NM * 3));
        const float4* cg4 = (const float4*)(ctrl_gt   + (size_t)b * (NM * NM * 3));
        float4* sC4w = (float4*)sCf;
        int k = 3 * tid;
        float4 p0 = __ldcs(&cp4[k]), p1 = __ldcs(&cp4[k + 1]), p2 = __ldcs(&cp4[k + 2]);
        float4 g0 = __ldcs(&cg4[k]), g1 = __ldcs(&cg4[k + 1]), g2 = __ldcs(&cg4[k + 2]);
        sC4w[k] = p0; sC4w[k + 1] = p1; sC4w[k + 2] = p2;
        int c0 = 4 * tid;                  // first of 4 points
        float d;
        float ss0, ss1, ss2, ss3;
        d = p0.x - g0.x; ss0  = d * d;
        d = p0.y - g0.y; ss0 += d * d;
        d = p0.z - g0.z; ss0 += d * d;
        d = p0.w - g0.w; ss1  = d * d;
        d = p1.x - g1.x; ss1 += d * d;
        d = p1.y - g1.y; ss1 += d * d;
        d = p1.z - g1.z; ss2  = d * d;
        d = p1.w - g1.w; ss2 += d * d;
        d = p2.x - g2.x; ss2 += d * d;
        d = p2.y - g2.y; ss3  = d * d;
        d = p2.z - g2.z; ss3 += d * d;
        d = p2.w - g2.w; ss3 += d * d;
        int i0 = (c0    ) >> 5, j0 = (c0    ) & 31;
        int i1 = (c0 + 1) >> 5, j1 = (c0 + 1) & 31;
        int i2 = (c0 + 2) >> 5, j2 = (c0 + 2) & 31;
        int i3 = (c0 + 3) >> 5, j3 = (c0 + 3) & 31;
        if (i0 < mu && j0 < mv) lc += ss0;
        if (i1 < mu && j1 < mv) lc += ss1;
        if (i2 < mu && j2 < mv) lc += ss2;
        if (i3 < mu && j3 < mv) lc += ss3;
    }

    // ---- local de Boor: 4 nonzero weights, denominator folded in ----
    if (tid < 128) {
        int dim = tid >> 6, g = tid & 63;
        int m = dim ? mv : mu;
        float x = EPSI + ((1.0f - 2.0f * EPSI) / 63.0f) * (float)g;
        int s = (int)(x * (float)(m + DEG));
        s = max(s, DEG); s = min(s, m - 1);
        while (s < m - 1 && x >= kvf(s + 1, m)) s++;
        while (s > DEG && x < kvf(s, m)) s--;
        float N[4]; N[0] = 1.0f; N[1] = N[2] = N[3] = 0.0f;
        float left[4], right[4];
#pragma unroll
        for (int d = 1; d <= DEG; d++) {
            left[d]  = x - kvf(s + 1 - d, m);
            right[d] = kvf(s + d, m) - x;
            float saved = 0.0f;
#pragma unroll
            for (int r = 0; r < d; r++) {
                float tmp = N[r] / (right[r + 1] + left[d - r]);
                N[r] = saved + right[r + 1] * tmp;
                saved = left[d - r] * tmp;
            }
            N[d] = saved;
        }
        float inv = 1.0f / (N[0] + N[1] + N[2] + N[3]);  // partition denom
        float4 w = make_float4(N[0] * inv, N[1] * inv, N[2] * inv, N[3] * inv);
        if (dim == 0) { wU4[g] = w; baseU[g] = s - DEG; }
        else          { wV4[g] = w; baseV[g] = s - DEG; }
    }
    __syncthreads();   // the ONLY block barrier: sCf + weights ready

    // ---- fused stage 1+2: each warp owns u = 8*warp + k, k=0..7.
    //      T tile lives in a per-warp double-buffered 96-float smem slab. ----
    float ls = 0.0f;
    {
        const int v0 = 2 * lane, v1 = v0 + 1;
        const float4 w0 = wV4[v0],  w1 = wV4[v1];
        const int    jv0 = 3 * baseV[v0], jv1 = 3 * baseV[v1];
        float* twb = sT + warp * 192;
        const float* xb = xyz + (size_t)b * (NU * NU * 3);

        // xyz prefetch for k=0
        const float2* p = (const float2*)(xb + (warp * 8) * 192 + 6 * lane);
        float2 A0 = __ldcs(p), A1 = __ldcs(p + 1), A2 = __ldcs(p + 2);

#pragma unroll
        for (int k = 0; k < 8; k++) {
            const int u = warp * 8 + k;
            float* tw = twb + (k & 1) * 96;

            // stage 1: lane j computes T[u][j] (j < mv)
            if (lane < mv) {
                float4 wu = wU4[u];
                const float* cc = &sCf[(baseU[u] * NM + lane) * 3];
                // bank = (3*lane + d) mod 32, gcd(3,32)=1 -> conflict-free
                tw[lane * 3 + 0] = wu.x * cc[0] + wu.y * cc[96] + wu.z * cc[192] + wu.w * cc[288];
                tw[lane * 3 + 1] = wu.x * cc[1] + wu.y * cc[97] + wu.z * cc[193] + wu.w * cc[289];
                tw[lane * 3 + 2] = wu.x * cc[2] + wu.y * cc[98] + wu.z * cc[194] + wu.w * cc[290];
            }
            __syncwarp();

            float2 C0 = A0, C1 = A1, C2 = A2;
            if (k < 7) {
                const float2* pn = (const float2*)(xb + (u + 1) * 192 + 6 * lane);
                A0 = __ldcs(pn); A1 = __ldcs(pn + 1); A2 = __ldcs(pn + 2);
            }

            // stage 2: lane evaluates v0, v1 (sparse 4-term j-gather, stride 3)
            float n00 = w0.x * tw[jv0]     + w0.y * tw[jv0 + 3] + w0.z * tw[jv0 + 6] + w0.w * tw[jv0 + 9];
            float n01 = w0.x * tw[jv0 + 1] + w0.y * tw[jv0 + 4] + w0.z * tw[jv0 + 7] + w0.w * tw[jv0 + 10];
            float n02 = w0.x * tw[jv0 + 2] + w0.y * tw[jv0 + 5] + w0.z * tw[jv0 + 8] + w0.w * tw[jv0 + 11];
            float n10 = w1.x * tw[jv1]     + w1.y * tw[jv1 + 3] + w1.z * tw[jv1 + 6] + w1.w * tw[jv1 + 9];
            float n11 = w1.x * tw[jv1 + 1] + w1.y * tw[jv1 + 4] + w1.z * tw[jv1 + 7] + w1.w * tw[jv1 + 10];
            float n12 = w1.x * tw[jv1 + 2] + w1.y * tw[jv1 + 5] + w1.z * tw[jv1 + 8] + w1.w * tw[jv1 + 11];
            float e;
            e = n00 - C0.x; ls += e * e;   // point v0 = (C0.x, C0.y, C1.x)
            e = n01 - C0.y; ls += e * e;
            e = n02 - C1.x; ls += e * e;
            e = n10 - C1.y; ls += e * e;   // point v1 = (C1.y, C2.x, C2.y)
            e = n11 - C2.x; ls += e * e;
            e = n12 - C2.y; ls += e * e;
            // NaN/Inf in surf propagates into ls; guard evaluated at end
        }
    }

    // ---- block reduction -> per-block partial ----
#pragma unroll
    for (int o = 16; o > 0; o >>= 1) {
        ls += __shfl_down_sync(0xffffffffu, ls, o);
        lc += __shfl_down_sync(0xffffffffu, lc, o);
    }
    if (lane == 0) { rS[warp] = ls; rC[warp] = lc; }
    __syncthreads();
    if (tid == 0) {
        float S = 0.0f, C = 0.0f;
#pragma unroll
        for (int i = 0; i < 8; i++) { S += rS[i]; C += rC[i]; }
        g_part[b] = make_float4(S, C, (float)(mu * mv), 0.0f);
        __threadfence();
        unsigned t = atomicAdd(&g_count, 1u);
        s_last = (t == BATCH - 1) ? 1 : 0;
    }
    __syncthreads();

    // ---- last block: global reduction + output (fused finalize) ----
    if (s_last) {
        __threadfence();
        double s = 0.0, c = 0.0, m = 0.0;
#pragma unroll
        for (int i = tid; i < BATCH; i += 256) {
            float4 pt = g_part[i];
            s += (double)pt.x; c += (double)pt.y; m += (double)pt.z;
        }
#pragma unroll
        for (int o = 16; o > 0; o >>= 1) {
            s += __shfl_down_sync(0xffffffffu, s, o);
            c += __shfl_down_sync(0xffffffffu, c, o);
            m += __shfl_down_sync(0xffffffffu, m, o);
        }
        __shared__ double dS[8], dC[8], dM[8];
        if (lane == 0) { dS[warp] = s; dC[warp] = c; dM[warp] = m; }
        __syncthreads();
        if (tid == 0) {
            double S = 0.0, C = 0.0, M = 0.0;
#pragma unroll
            for (int i = 0; i < 8; i++) { S += dS[i]; C += dC[i]; M += dM[i]; }
            double denom = M * 3.0; if (denom < 1.0) denom = 1.0;
            double loss_ctrl = C / denom;
            double loss_surf = S / (double)((long long)BATCH * NU * NU * 3);
            float lcf = (float)loss_ctrl;
            float lsf = (float)loss_surf;
            out[0] = lcf + lsf;                 // total (pre nan-guard, W=1)
            out[1] = lcf;                       // loss_ctrl
            unsigned ub = __float_as_uint(lsf);
            bool bad = ((ub & 0x7f800000u) == 0x7f800000u);
            out[2] = bad ? 1e6f : lsf;          // surf_mse (guarded)
            g_count = 0;                        // reset for next graph replay
        }
    }
}

extern "C" void kernel_launch(void* const* d_in, const int* in_sizes, int n_in,
                              void* d_out, int out_size) {
    const float* ctrl_pred = (const float*)d_in[0];   // (B,32,32,3)
    const float* ctrl_gt   = (const float*)d_in[1];   // (B,32,32,3)
    const float* mask      = (const float*)d_in[2];   // (B,32,32)
    const float* xyz       = (const float*)d_in[3];   // (B,64,64,3)
    float* out = (float*)d_out;

    size_t smem_bytes = SMEM_FLOATS * sizeof(float);  // 20992 B
    cudaFuncSetAttribute(surf_loss_kernel,
                         cudaFuncAttributeMaxDynamicSharedMemorySize,
                         (int)smem_bytes);

    surf_loss_kernel<<<BATCH, 256, smem_bytes>>>(ctrl_pred, ctrl_gt, mask, xyz, out);
}